// round 12
// baseline (speedup 1.0000x reference)
#include <cuda_runtime.h>
#include <cuda_fp16.h>
#include <math.h>

#define Bz 2
#define Tz 1024
#define Cz 1024
#define Hz 16
#define HSz 64

// ---------------- scratch ----------------
__device__ __half  g_xsh[Bz * Tz * Cz];
__device__ __half  g_Wqh[Cz * Cz];
__device__ __half  g_Wkh[Cz * Cz];
__device__ __half  g_Wvh[Cz * Cz];
__device__ __half  g_Woh[Cz * Cz];
__device__ __half  g_qh[Bz * Tz * Cz];
__device__ __half  g_kh[Bz * Tz * Cz];
__device__ __half  g_vh[Bz * Tz * Cz];
__device__ __half  g_S [(size_t)Bz * Hz * Tz * Tz];
__device__ __half  g_M2[(size_t)Bz * Hz * Tz * Tz];
__device__ __half  g_yh[Bz * Tz * Cz];
__device__ float   g_ropec[Tz * 16];
__device__ float   g_ropes[Tz * 16];

__device__ __forceinline__ unsigned packh2(float a, float b) {
    __half2 h = __floats2half2_rn(a, b);
    return *(unsigned*)&h;
}
__device__ __forceinline__ void cpa16(unsigned dst, const void* src) {
    asm volatile("cp.async.cg.shared.global [%0], [%1], 16;" :: "r"(dst), "l"(src));
}
__device__ __forceinline__ void cpcommit() {
    asm volatile("cp.async.commit_group;");
}

// ---------------- prep: rope table ----------------
__global__ __launch_bounds__(256) void rope_tab() {
    int i = blockIdx.x * 256 + threadIdx.x;    // 16384
    int j = i & 15;
    int t = i >> 4;
    float ang = (float)t * exp2f(-0.625f * (float)j);
    float s, c;
    sincosf(ang, &s, &c);
    g_ropec[i] = c;
    g_ropes[i] = s;
}

// ---------------- prep: shift + cvt ----------------
__global__ __launch_bounds__(256) void shift_cvt4(const float* __restrict__ x,
                                                  __half* __restrict__ xsh) {
    int idx = blockIdx.x * 256 + threadIdx.x;
    int c4 = idx & 255;
    int t = (idx >> 8) & 1023;
    int b = idx >> 18;
    int c = c4 * 4;
    float4 val;
    if (c < 512) {
        if (t == 0) val = make_float4(0.f, 0.f, 0.f, 0.f);
        else        val = *(const float4*)(x + ((size_t)b * Tz + t - 1) * Cz + c);
    } else {
        val = *(const float4*)(x + ((size_t)b * Tz + t) * Cz + c);
    }
    uint2 o = make_uint2(packh2(val.x, val.y), packh2(val.z, val.w));
    ((uint2*)xsh)[idx] = o;
}

// ---------------- prep: convert 4 weight matrices fp32 -> half -----------------
__global__ __launch_bounds__(256) void wcvt(const float* __restrict__ Wq,
                                            const float* __restrict__ Wk,
                                            const float* __restrict__ Wv,
                                            const float* __restrict__ Wo,
                                            __half* __restrict__ Hq,
                                            __half* __restrict__ Hk,
                                            __half* __restrict__ Hv,
                                            __half* __restrict__ Ho) {
    int idx = blockIdx.x * 256 + threadIdx.x;
    int which = idx >> 17;
    int g = idx & 131071;
    const float* W = which == 0 ? Wq : which == 1 ? Wk : which == 2 ? Wv : Wo;
    __half* H = which == 0 ? Hq : which == 1 ? Hk : which == 2 ? Hv : Ho;
    float4 a = *(const float4*)(W + (size_t)g * 8);
    float4 b = *(const float4*)(W + (size_t)g * 8 + 4);
    uint4 o;
    o.x = packh2(a.x, a.y); o.y = packh2(a.z, a.w);
    o.z = packh2(b.x, b.y); o.w = packh2(b.z, b.w);
    *(uint4*)(H + (size_t)g * 8) = o;
}

// ---------------- persistent cp.async + ldmatrix fp16 GEMM ----------------
// BT=0: B [k][n] row-major (trans ldmatrix);  BT=1: B [n][k] row-major.
// MODE 0: QKV (half out, scatter + bias + fused RoPE)
// MODE 1: output (fp32, (acc+bias)*gamma)
// MODE 2: scores (half out, *0.125), BT=1
// MODE 3: PV (half out)
template <int MODE, int TN, int KD, int LDA, int LDB, int BT, int TX, int TY, int TZ>
__global__ __launch_bounds__(256, 2) void gemm_h(
    const __half* __restrict__ A0,
    const __half* __restrict__ B0, const __half* __restrict__ B1, const __half* __restrict__ B2,
    const float* __restrict__ bias0, const float* __restrict__ bias1, const float* __restrict__ bias2,
    float* __restrict__ O0, float* __restrict__ O1, float* __restrict__ O2,
    const float* __restrict__ gamma)
{
    constexpr int PBH = TN + 8;
    constexpr int ASTB = 128 * 80;
    constexpr int BSTB = (BT == 1) ? TN * 80 : 32 * PBH * 2;
    constexpr int PANELS = KD / 32;
    constexpr int STAGES = 4;
    constexpr int WNT = TN / 4;
    constexpr int NT = WNT / 8;
    constexpr int NCH = (TN == 128) ? 2 : 1;
    constexpr int NTILES = TX * TY * TZ;

    extern __shared__ unsigned char shm[];
    unsigned ash_s = (unsigned)__cvta_generic_to_shared(shm);
    unsigned bsh_s = ash_s + STAGES * ASTB;

    int tid = threadIdx.x;
    int lane = tid & 31, wid = tid >> 5;
    int wm = wid >> 2, wn = wid & 3;
    int r = lane >> 2, c = lane & 3;
    int lrow = lane & 15;
    int lk = (lane >> 4) & 1;

    for (int tile = blockIdx.x; tile < NTILES; tile += gridDim.x) {
        int bx = tile % TX;
        int rem = tile / TX;
        int by = rem % TY;
        int z = rem / TY;
        int bm = by * 128;
        int bnL = bx * TN;

        const __half* Ab = A0;
        const __half* Bb = B0;
        const float* bias = bias0;
        float* Out = O0;
        int bn = bnL;
        int which = 0;
        if constexpr (MODE == 0) {
            which = bnL >> 10;
            bn = bnL & 1023;
            Bb   = which == 0 ? B0 : (which == 1 ? B1 : B2);
            bias = which == 0 ? bias0 : (which == 1 ? bias1 : bias2);
            Out  = which == 0 ? O0 : (which == 1 ? O1 : O2);
        } else if constexpr (MODE == 2) {
            Ab = A0 + (size_t)z * Tz * HSz;
            Bb = B0 + (size_t)z * Tz * HSz;
        } else if constexpr (MODE == 3) {
            Ab = A0 + (size_t)z * Tz * Tz;
            Bb = B0 + (size_t)z * Tz * HSz;
        }

        auto issue = [&](int p) {
            int st = p & (STAGES - 1);
            unsigned ab = ash_s + st * ASTB;
#pragma unroll
            for (int j = 0; j < 2; j++) {
                int idx = tid + j * 256;
                int row = idx >> 2, kq = idx & 3;
                cpa16(ab + (unsigned)(row * 80 + kq * 16),
                      Ab + (size_t)(bm + row) * LDA + p * 32 + kq * 8);
            }
            unsigned bb = bsh_s + st * BSTB;
            if constexpr (BT == 1) {
#pragma unroll
                for (int j = 0; j < NCH; j++) {
                    int idx = tid + j * 256;
                    int row = idx >> 2, kq = idx & 3;
                    cpa16(bb + (unsigned)(row * 80 + kq * 16),
                          Bb + (size_t)(bn + row) * LDB + p * 32 + kq * 8);
                }
            } else {
#pragma unroll
                for (int j = 0; j < NCH; j++) {
                    int idx = tid + j * 256;
                    int row = (TN == 128) ? (idx >> 4) : (idx >> 3);
                    int ch  = idx & (TN / 8 - 1);
                    cpa16(bb + (unsigned)(row * PBH + ch * 8) * 2,
                          Bb + (size_t)(p * 32 + row) * LDB + bn + ch * 8);
                }
            }
        };

        float acc[4][NT][4];
#pragma unroll
        for (int mi = 0; mi < 4; mi++)
#pragma unroll
            for (int ni = 0; ni < NT; ni++)
#pragma unroll
                for (int l = 0; l < 4; l++) acc[mi][ni][l] = 0.f;

#pragma unroll
        for (int s = 0; s < 3; s++) {
            if (s < PANELS) issue(s);
            cpcommit();
        }

        for (int p = 0; p < PANELS; p++) {
            asm volatile("cp.async.wait_group 2;");
            __syncthreads();
            int st = p & (STAGES - 1);
            unsigned abase = ash_s + st * ASTB;
            unsigned bbase = bsh_s + st * BSTB;
#pragma unroll
            for (int ks = 0; ks < 2; ks++) {
                unsigned af[4][4];
#pragma unroll
                for (int mi = 0; mi < 4; mi++) {
                    int row = wm * 64 + mi * 16 + lrow;
                    unsigned addr = abase + (unsigned)(row * 80 + (ks * 16 + lk * 8) * 2);
                    asm volatile(
                        "ldmatrix.sync.aligned.m8n8.x4.shared.b16 {%0,%1,%2,%3},[%4];"
                        : "=r"(af[mi][0]), "=r"(af[mi][1]),
                          "=r"(af[mi][2]), "=r"(af[mi][3])
                        : "r"(addr));
                }
                unsigned bf[NT][2];
                if constexpr (BT == 1) {
                    unsigned brow = bbase +
                        (unsigned)((wn * WNT + (lane & 7)) * 80 +
                                   (ks * 16 + ((lane >> 3) & 1) * 8) * 2);
#pragma unroll
                    for (int ni = 0; ni < NT; ni++) {
                        asm volatile(
                            "ldmatrix.sync.aligned.m8n8.x2.shared.b16 {%0,%1},[%2];"
                            : "=r"(bf[ni][0]), "=r"(bf[ni][1])
                            : "r"(brow + ni * 640));
                    }
                } else {
                    unsigned brow = bbase + (unsigned)((ks * 16 + lrow) * PBH + wn * WNT) * 2;
#pragma unroll
                    for (int ni = 0; ni < NT; ni++) {
                        asm volatile(
                            "ldmatrix.sync.aligned.m8n8.x2.trans.shared.b16 {%0,%1},[%2];"
                            : "=r"(bf[ni][0]), "=r"(bf[ni][1])
                            : "r"(brow + ni * 16));
                    }
                }
#pragma unroll
                for (int mi = 0; mi < 4; mi++)
#pragma unroll
                    for (int ni = 0; ni < NT; ni++)
                        asm volatile(
                            "mma.sync.aligned.m16n8k16.row.col.f32.f16.f16.f32 "
                            "{%0,%1,%2,%3},{%4,%5,%6,%7},{%8,%9},{%0,%1,%2,%3};"
                            : "+f"(acc[mi][ni][0]), "+f"(acc[mi][ni][1]),
                              "+f"(acc[mi][ni][2]), "+f"(acc[mi][ni][3])
                            : "r"(af[mi][0]), "r"(af[mi][1]),
                              "r"(af[mi][2]), "r"(af[mi][3]),
                              "r"(bf[ni][0]), "r"(bf[ni][1]));
            }
            if (p + 3 < PANELS) issue(p + 3);
            cpcommit();
        }

        if constexpr (MODE == 0) {
            bool doRot = (which <= 1) && ((wn & 1) == 0);
#pragma unroll
            for (int mi = 0; mi < 4; mi++) {
#pragma unroll
                for (int half = 0; half < 2; half++) {
                    int row = bm + wm * 64 + mi * 16 + r + half * 8;
                    int b = row >> 10, t = row & 1023;
                    float vals[NT][2];
#pragma unroll
                    for (int ni = 0; ni < NT; ni++) {
                        int colt = bn + wn * WNT + ni * 8 + c * 2;
                        vals[ni][0] = acc[mi][ni][half * 2 + 0] + bias[colt];
                        vals[ni][1] = acc[mi][ni][half * 2 + 1] + bias[colt + 1];
                    }
                    if (doRot) {
#pragma unroll
                        for (int ni = 0; ni < 2; ni++) {
                            int j0 = ni * 8 + c * 2;
                            float c0 = g_ropec[t * 16 + j0], s0 = g_ropes[t * 16 + j0];
                            float c1 = g_ropec[t * 16 + j0 + 1], s1 = g_ropes[t * 16 + j0 + 1];
                            float x0 = vals[ni][0], x1 = vals[ni][1];
                            float y0 = vals[ni + 2][0], y1 = vals[ni + 2][1];
                            vals[ni][0] = x0 * c0 - y0 * s0;
                            vals[ni][1] = x1 * c1 - y1 * s1;
                            vals[ni + 2][0] = y0 * c0 + x0 * s0;
                            vals[ni + 2][1] = y1 * c1 + x1 * s1;
                        }
                    }
#pragma unroll
                    for (int ni = 0; ni < NT; ni++) {
                        int colt = bn + wn * WNT + ni * 8 + c * 2;
                        int h = colt >> 6, d = colt & 63;
                        unsigned* Ow = (unsigned*)Out;
                        size_t hidx = (((size_t)b * Hz + h) * Tz + t) * HSz + d;
                        Ow[hidx >> 1] = packh2(vals[ni][0], vals[ni][1]);
                    }
                }
            }
        } else {
#pragma unroll
            for (int mi = 0; mi < 4; mi++) {
#pragma unroll
                for (int ni = 0; ni < NT; ni++) {
#pragma unroll
                    for (int half = 0; half < 2; half++) {
                        int row = bm + wm * 64 + mi * 16 + r + half * 8;
                        int colt = bn + wn * WNT + ni * 8 + c * 2;
                        float v0 = acc[mi][ni][half * 2 + 0];
                        float v1 = acc[mi][ni][half * 2 + 1];
                        if constexpr (MODE == 1) {
                            int t = row & 1023;
                            float gm = gamma[t];
                            float2 o = make_float2((v0 + bias[colt]) * gm,
                                                   (v1 + bias[colt + 1]) * gm);
                            *(float2*)(Out + (size_t)row * Cz + colt) = o;
                        } else if constexpr (MODE == 2) {
                            unsigned* Sw = (unsigned*)Out;
                            size_t hidx = (size_t)z * Tz * Tz + (size_t)row * Tz + colt;
                            Sw[hidx >> 1] = packh2(v0 * 0.125f, v1 * 0.125f);
                        } else {
                            int b = z >> 4, g = z & 15;
                            unsigned* yw = (unsigned*)Out;
                            size_t hidx = ((size_t)b * Tz + row) * Cz + g * HSz + colt;
                            yw[hidx >> 1] = packh2(v0, v1);
                        }
                    }
                }
            }
        }
        __syncthreads();
    }
}

// ---------------- softmax + w + tensor-core head-mix ----------------
__global__ __launch_bounds__(512) void softmax_mix(
    const __half* __restrict__ S, unsigned* __restrict__ M2w,
    const float* __restrict__ tw, const float* __restrict__ alpha,
    const float* __restrict__ beta, const float* __restrict__ Wmix)
{
    constexpr int PADH = 1032;
    __shared__ __half P[16][PADH];
    __shared__ __half Wh[16][24];
    int t = blockIdx.x, b = blockIdx.y;
    int tid = threadIdx.x, lane = tid & 31, h = tid >> 5;

    if (tid < 256) Wh[tid >> 4][tid & 15] = __float2half(Wmix[tid]);

    const uint4* row = (const uint4*)(S + (((size_t)b * Hz + h) * Tz + t) * Tz);
    float vals[32];
    float mx = -1e30f;
#pragma unroll
    for (int j = 0; j < 4; j++) {
        uint4 u = row[lane + j * 32];
        unsigned uu[4] = {u.x, u.y, u.z, u.w};
#pragma unroll
        for (int q = 0; q < 4; q++) {
            float2 f = __half22float2(*(__half2*)&uu[q]);
            vals[j * 8 + 2 * q]     = f.x;
            vals[j * 8 + 2 * q + 1] = f.y;
            mx = fmaxf(mx, fmaxf(f.x, f.y));
        }
    }
#pragma unroll
    for (int o = 16; o; o >>= 1) mx = fmaxf(mx, __shfl_xor_sync(~0u, mx, o));
    float sum = 0.f;
#pragma unroll
    for (int l = 0; l < 32; l++) {
        vals[l] = __expf(vals[l] - mx);
        sum += vals[l];
    }
#pragma unroll
    for (int o = 16; o; o >>= 1) sum += __shfl_xor_sync(~0u, sum, o);
    float bt = beta[h * Tz + t] / sum;
#pragma unroll
    for (int j = 0; j < 4; j++) {
        int s0 = (lane + j * 32) * 8;
        unsigned wv[4];
#pragma unroll
        for (int q = 0; q < 4; q++) {
            int sa = s0 + 2 * q, sb = s0 + 2 * q + 1;
            float wa = 0.f, wb = 0.f;
            if (sa <= t) wa = tw[h * Tz + 1023 + sa - t] * alpha[h * Tz + sa] * bt;
            if (sb <= t) wb = tw[h * Tz + 1023 + sb - t] * alpha[h * Tz + sb] * bt;
            wv[q] = packh2(vals[j * 8 + 2 * q] * wa, vals[j * 8 + 2 * q + 1] * wb);
        }
        *(uint4*)&P[h][s0] = *(uint4*)wv;
    }
    __syncthreads();
    {
        int r = lane >> 2, c = lane & 3;
        unsigned arow = (lane & 7) + ((lane >> 3) & 1) * 8;
        unsigned acol = (lane >> 4) * 8;
        unsigned aaddr = (unsigned)__cvta_generic_to_shared(&Wh[arow][acol]);
        unsigned af0, af1, af2, af3;
        asm volatile("ldmatrix.sync.aligned.m8n8.x4.shared.b16 {%0,%1,%2,%3},[%4];"
                     : "=r"(af0), "=r"(af1), "=r"(af2), "=r"(af3) : "r"(aaddr));
        size_t orow0 = ((size_t)b * Hz) * Tz + t;
#pragma unroll
        for (int n8 = 0; n8 < 8; n8++) {
            int s0 = h * 64 + n8 * 8;
            unsigned baddr = (unsigned)__cvta_generic_to_shared(&P[lane & 15][s0]);
            unsigned bf0, bf1;
            asm volatile("ldmatrix.sync.aligned.m8n8.x2.trans.shared.b16 {%0,%1},[%2];"
                         : "=r"(bf0), "=r"(bf1) : "r"(baddr));
            float d0 = 0.f, d1 = 0.f, d2 = 0.f, d3 = 0.f;
            asm volatile(
                "mma.sync.aligned.m16n8k16.row.col.f32.f16.f16.f32 "
                "{%0,%1,%2,%3},{%4,%5,%6,%7},{%8,%9},{%0,%1,%2,%3};"
                : "+f"(d0), "+f"(d1), "+f"(d2), "+f"(d3)
                : "r"(af0), "r"(af1), "r"(af2), "r"(af3), "r"(bf0), "r"(bf1));
            int sw = (s0 >> 1) + c;
            M2w[(orow0 + (size_t)r * Tz) * (Tz / 2) + sw]       = packh2(d0, d1);
            M2w[(orow0 + (size_t)(r + 8) * Tz) * (Tz / 2) + sw] = packh2(d2, d3);
        }
    }
}

// ---------------- launch ----------------
extern "C" void kernel_launch(void* const* d_in, const int* in_sizes, int n_in,
                              void* d_out, int out_size) {
    const float* x          = (const float*)d_in[0];
    const float* time_w     = (const float*)d_in[1];
    const float* time_alpha = (const float*)d_in[2];
    const float* time_beta  = (const float*)d_in[3];
    const float* time_gamma = (const float*)d_in[4];
    const float* Wq = (const float*)d_in[5];
    const float* bq = (const float*)d_in[6];
    const float* Wk = (const float*)d_in[7];
    const float* bk = (const float*)d_in[8];
    const float* Wv = (const float*)d_in[9];
    const float* bv = (const float*)d_in[10];
    const float* Wmix = (const float*)d_in[11];
    const float* Wo = (const float*)d_in[12];
    const float* bo = (const float*)d_in[13];
    float* out = (float*)d_out;

    __half *xsh, *Wqh, *Wkh, *Wvh, *Woh, *qh, *kh, *vh, *S, *M2, *yh;
    cudaGetSymbolAddress((void**)&xsh, g_xsh);
    cudaGetSymbolAddress((void**)&Wqh, g_Wqh);
    cudaGetSymbolAddress((void**)&Wkh, g_Wkh);
    cudaGetSymbolAddress((void**)&Wvh, g_Wvh);
    cudaGetSymbolAddress((void**)&Woh, g_Woh);
    cudaGetSymbolAddress((void**)&qh, g_qh);
    cudaGetSymbolAddress((void**)&kh, g_kh);
    cudaGetSymbolAddress((void**)&vh, g_vh);
    cudaGetSymbolAddress((void**)&S,  g_S);
    cudaGetSymbolAddress((void**)&M2, g_M2);
    cudaGetSymbolAddress((void**)&yh, g_yh);

    constexpr int SM128 = 4 * 128 * 80 + 4 * 32 * 136 * 2;   // 75776
    constexpr int SMSC  = 4 * 128 * 80 + 4 * 128 * 80;       // 81920
    constexpr int SM64  = 4 * 128 * 80 + 4 * 32 * 72 * 2;    // 59392

    cudaFuncSetAttribute((const void*)gemm_h<0, 128, 1024, 1024, 1024, 0, 24, 16, 1>,
                         cudaFuncAttributeMaxDynamicSharedMemorySize, SM128);
    cudaFuncSetAttribute((const void*)gemm_h<1, 128, 1024, 1024, 1024, 0, 8, 16, 1>,
                         cudaFuncAttributeMaxDynamicSharedMemorySize, SM128);
    cudaFuncSetAttribute((const void*)gemm_h<2, 128, 64, 64, 64, 1, 8, 8, 32>,
                         cudaFuncAttributeMaxDynamicSharedMemorySize, SMSC);
    cudaFuncSetAttribute((const void*)gemm_h<3, 64, 1024, 1024, 64, 0, 1, 8, 32>,
                         cudaFuncAttributeMaxDynamicSharedMemorySize, SM64);

    rope_tab<<<64, 256>>>();
    shift_cvt4<<<(Bz * Tz * Cz / 4) / 256, 256>>>(x, xsh);
    wcvt<<<(4 * 131072) / 256, 256>>>(Wq, Wk, Wv, Wo, Wqh, Wkh, Wvh, Woh);

    // QKV: exact grid (384 CTAs) — persistent loop runs once per CTA
    gemm_h<0, 128, 1024, 1024, 1024, 0, 24, 16, 1><<<384, 256, SM128>>>(
        xsh, Wqh, Wkh, Wvh, bq, bk, bv, (float*)qh, (float*)kh, (float*)vh, nullptr);

    // scores: 2048 tiles on 304 persistent CTAs (this split measured best)
    gemm_h<2, 128, 64, 64, 64, 1, 8, 8, 32><<<304, 256, SMSC>>>(
        qh, kh, nullptr, nullptr, nullptr, nullptr, nullptr, (float*)S, nullptr, nullptr, nullptr);

    softmax_mix<<<dim3(Tz, Bz), 512>>>(S, (unsigned*)M2, time_w, time_alpha,
                                       time_beta, Wmix);

    // PV: exact grid
    gemm_h<3, 64, 1024, 1024, 64, 0, 1, 8, 32><<<256, 256, SM64>>>(
        M2, vh, nullptr, nullptr, nullptr, nullptr, nullptr, (float*)yh, nullptr, nullptr, nullptr);

    // output: exact grid
    gemm_h<1, 128, 1024, 1024, 1024, 0, 8, 16, 1><<<128, 256, SM128>>>(
        yh, Woh, nullptr, nullptr, bo, nullptr, nullptr, out, nullptr, nullptr, time_gamma);
}

// round 13
// speedup vs baseline: 1.0458x; 1.0458x over previous
#include <cuda_runtime.h>
#include <cuda_fp16.h>
#include <math.h>

#define Bz 2
#define Tz 1024
#define Cz 1024
#define Hz 16
#define HSz 64

// ---------------- scratch ----------------
__device__ __half  g_xsh[Bz * Tz * Cz];
__device__ __half  g_Wqh[Cz * Cz];
__device__ __half  g_Wkh[Cz * Cz];
__device__ __half  g_Wvh[Cz * Cz];
__device__ __half  g_Woh[Cz * Cz];
__device__ __half  g_qh[Bz * Tz * Cz];
__device__ __half  g_kh[Bz * Tz * Cz];
__device__ __half  g_vh[Bz * Tz * Cz];
__device__ __half  g_S [(size_t)Bz * Hz * Tz * Tz];
__device__ __half  g_M2[(size_t)Bz * Hz * Tz * Tz];
__device__ __half  g_yh[Bz * Tz * Cz];
__device__ float   g_ropec[Tz * 16];
__device__ float   g_ropes[Tz * 16];

__device__ __forceinline__ unsigned packh2(float a, float b) {
    __half2 h = __floats2half2_rn(a, b);
    return *(unsigned*)&h;
}
__device__ __forceinline__ void cpa16(unsigned dst, const void* src) {
    asm volatile("cp.async.cg.shared.global [%0], [%1], 16;" :: "r"(dst), "l"(src));
}
__device__ __forceinline__ void cpcommit() {
    asm volatile("cp.async.commit_group;");
}

// ---------------- prep: rope table ----------------
__global__ __launch_bounds__(256) void rope_tab() {
    int i = blockIdx.x * 256 + threadIdx.x;    // 16384
    int j = i & 15;
    int t = i >> 4;
    float ang = (float)t * exp2f(-0.625f * (float)j);
    float s, c;
    sincosf(ang, &s, &c);
    g_ropec[i] = c;
    g_ropes[i] = s;
}

// ---------------- prep: shift + cvt ----------------
__global__ __launch_bounds__(256) void shift_cvt4(const float* __restrict__ x,
                                                  __half* __restrict__ xsh) {
    int idx = blockIdx.x * 256 + threadIdx.x;
    int c4 = idx & 255;
    int t = (idx >> 8) & 1023;
    int b = idx >> 18;
    int c = c4 * 4;
    float4 val;
    if (c < 512) {
        if (t == 0) val = make_float4(0.f, 0.f, 0.f, 0.f);
        else        val = *(const float4*)(x + ((size_t)b * Tz + t - 1) * Cz + c);
    } else {
        val = *(const float4*)(x + ((size_t)b * Tz + t) * Cz + c);
    }
    uint2 o = make_uint2(packh2(val.x, val.y), packh2(val.z, val.w));
    ((uint2*)xsh)[idx] = o;
}

// ---------------- prep: convert 4 weight matrices fp32 -> half -----------------
__global__ __launch_bounds__(256) void wcvt(const float* __restrict__ Wq,
                                            const float* __restrict__ Wk,
                                            const float* __restrict__ Wv,
                                            const float* __restrict__ Wo,
                                            __half* __restrict__ Hq,
                                            __half* __restrict__ Hk,
                                            __half* __restrict__ Hv,
                                            __half* __restrict__ Ho) {
    int idx = blockIdx.x * 256 + threadIdx.x;
    int which = idx >> 17;
    int g = idx & 131071;
    const float* W = which == 0 ? Wq : which == 1 ? Wk : which == 2 ? Wv : Wo;
    __half* H = which == 0 ? Hq : which == 1 ? Hk : which == 2 ? Hv : Ho;
    float4 a = *(const float4*)(W + (size_t)g * 8);
    float4 b = *(const float4*)(W + (size_t)g * 8 + 4);
    uint4 o;
    o.x = packh2(a.x, a.y); o.y = packh2(a.z, a.w);
    o.z = packh2(b.x, b.y); o.w = packh2(b.z, b.w);
    *(uint4*)(H + (size_t)g * 8) = o;
}

// ---------------- persistent cp.async + ldmatrix fp16 GEMM ----------------
// BT=0: B [k][n] row-major (trans ldmatrix);  BT=1: B [n][k] row-major.
// CAUSAL=1 (PV): k-panels limited to (by+1)*4 (M2 causal: zero for s>t).
// MODE 0: QKV (half out, scatter + bias + fused RoPE)
// MODE 1: output (fp32, (acc+bias)*gamma)
// MODE 2: scores (half out, *0.125), BT=1
// MODE 3: PV (half out)
template <int MODE, int TN, int KD, int LDA, int LDB, int BT, int TX, int TY, int TZ,
          int CAUSAL>
__global__ __launch_bounds__(256, 2) void gemm_h(
    const __half* __restrict__ A0,
    const __half* __restrict__ B0, const __half* __restrict__ B1, const __half* __restrict__ B2,
    const float* __restrict__ bias0, const float* __restrict__ bias1, const float* __restrict__ bias2,
    float* __restrict__ O0, float* __restrict__ O1, float* __restrict__ O2,
    const float* __restrict__ gamma)
{
    constexpr int PBH = TN + 8;
    constexpr int ASTB = 128 * 80;
    constexpr int BSTB = (BT == 1) ? TN * 80 : 32 * PBH * 2;
    constexpr int PANELS = KD / 32;
    constexpr int STAGES = 4;
    constexpr int WNT = TN / 4;
    constexpr int NT = WNT / 8;
    constexpr int NCH = (TN == 128) ? 2 : 1;
    constexpr int NTILES = TX * TY * TZ;

    extern __shared__ unsigned char shm[];
    unsigned ash_s = (unsigned)__cvta_generic_to_shared(shm);
    unsigned bsh_s = ash_s + STAGES * ASTB;

    int tid = threadIdx.x;
    int lane = tid & 31, wid = tid >> 5;
    int wm = wid >> 2, wn = wid & 3;
    int r = lane >> 2, c = lane & 3;
    int lrow = lane & 15;
    int lk = (lane >> 4) & 1;

    for (int tile = blockIdx.x; tile < NTILES; tile += gridDim.x) {
        int bx = tile % TX;
        int rem = tile / TX;
        int by = rem % TY;
        int z = rem / TY;
        int bm = by * 128;
        int bnL = bx * TN;

        int npan = CAUSAL ? (by + 1) * 4 : PANELS;

        const __half* Ab = A0;
        const __half* Bb = B0;
        const float* bias = bias0;
        float* Out = O0;
        int bn = bnL;
        int which = 0;
        if constexpr (MODE == 0) {
            which = bnL >> 10;
            bn = bnL & 1023;
            Bb   = which == 0 ? B0 : (which == 1 ? B1 : B2);
            bias = which == 0 ? bias0 : (which == 1 ? bias1 : bias2);
            Out  = which == 0 ? O0 : (which == 1 ? O1 : O2);
        } else if constexpr (MODE == 2) {
            Ab = A0 + (size_t)z * Tz * HSz;
            Bb = B0 + (size_t)z * Tz * HSz;
        } else if constexpr (MODE == 3) {
            Ab = A0 + (size_t)z * Tz * Tz;
            Bb = B0 + (size_t)z * Tz * HSz;
        }

        auto issue = [&](int p) {
            int st = p & (STAGES - 1);
            unsigned ab = ash_s + st * ASTB;
#pragma unroll
            for (int j = 0; j < 2; j++) {
                int idx = tid + j * 256;
                int row = idx >> 2, kq = idx & 3;
                cpa16(ab + (unsigned)(row * 80 + kq * 16),
                      Ab + (size_t)(bm + row) * LDA + p * 32 + kq * 8);
            }
            unsigned bb = bsh_s + st * BSTB;
            if constexpr (BT == 1) {
#pragma unroll
                for (int j = 0; j < NCH; j++) {
                    int idx = tid + j * 256;
                    int row = idx >> 2, kq = idx & 3;
                    cpa16(bb + (unsigned)(row * 80 + kq * 16),
                          Bb + (size_t)(bn + row) * LDB + p * 32 + kq * 8);
                }
            } else {
#pragma unroll
                for (int j = 0; j < NCH; j++) {
                    int idx = tid + j * 256;
                    int row = (TN == 128) ? (idx >> 4) : (idx >> 3);
                    int ch  = idx & (TN / 8 - 1);
                    cpa16(bb + (unsigned)(row * PBH + ch * 8) * 2,
                          Bb + (size_t)(p * 32 + row) * LDB + bn + ch * 8);
                }
            }
        };

        float acc[4][NT][4];
#pragma unroll
        for (int mi = 0; mi < 4; mi++)
#pragma unroll
            for (int ni = 0; ni < NT; ni++)
#pragma unroll
                for (int l = 0; l < 4; l++) acc[mi][ni][l] = 0.f;

#pragma unroll
        for (int s = 0; s < 3; s++) {
            if (s < npan) issue(s);
            cpcommit();
        }

        for (int p = 0; p < npan; p++) {
            asm volatile("cp.async.wait_group 2;");
            __syncthreads();
            int st = p & (STAGES - 1);
            unsigned abase = ash_s + st * ASTB;
            unsigned bbase = bsh_s + st * BSTB;
#pragma unroll
            for (int ks = 0; ks < 2; ks++) {
                unsigned af[4][4];
#pragma unroll
                for (int mi = 0; mi < 4; mi++) {
                    int row = wm * 64 + mi * 16 + lrow;
                    unsigned addr = abase + (unsigned)(row * 80 + (ks * 16 + lk * 8) * 2);
                    asm volatile(
                        "ldmatrix.sync.aligned.m8n8.x4.shared.b16 {%0,%1,%2,%3},[%4];"
                        : "=r"(af[mi][0]), "=r"(af[mi][1]),
                          "=r"(af[mi][2]), "=r"(af[mi][3])
                        : "r"(addr));
                }
                unsigned bf[NT][2];
                if constexpr (BT == 1) {
                    unsigned brow = bbase +
                        (unsigned)((wn * WNT + (lane & 7)) * 80 +
                                   (ks * 16 + ((lane >> 3) & 1) * 8) * 2);
#pragma unroll
                    for (int ni = 0; ni < NT; ni++) {
                        asm volatile(
                            "ldmatrix.sync.aligned.m8n8.x2.shared.b16 {%0,%1},[%2];"
                            : "=r"(bf[ni][0]), "=r"(bf[ni][1])
                            : "r"(brow + ni * 640));
                    }
                } else {
                    unsigned brow = bbase + (unsigned)((ks * 16 + lrow) * PBH + wn * WNT) * 2;
#pragma unroll
                    for (int ni = 0; ni < NT; ni++) {
                        asm volatile(
                            "ldmatrix.sync.aligned.m8n8.x2.trans.shared.b16 {%0,%1},[%2];"
                            : "=r"(bf[ni][0]), "=r"(bf[ni][1])
                            : "r"(brow + ni * 16));
                    }
                }
#pragma unroll
                for (int mi = 0; mi < 4; mi++)
#pragma unroll
                    for (int ni = 0; ni < NT; ni++)
                        asm volatile(
                            "mma.sync.aligned.m16n8k16.row.col.f32.f16.f16.f32 "
                            "{%0,%1,%2,%3},{%4,%5,%6,%7},{%8,%9},{%0,%1,%2,%3};"
                            : "+f"(acc[mi][ni][0]), "+f"(acc[mi][ni][1]),
                              "+f"(acc[mi][ni][2]), "+f"(acc[mi][ni][3])
                            : "r"(af[mi][0]), "r"(af[mi][1]),
                              "r"(af[mi][2]), "r"(af[mi][3]),
                              "r"(bf[ni][0]), "r"(bf[ni][1]));
            }
            if (p + 3 < npan) issue(p + 3);
            cpcommit();
        }

        if constexpr (MODE == 0) {
            bool doRot = (which <= 1) && ((wn & 1) == 0);
#pragma unroll
            for (int mi = 0; mi < 4; mi++) {
#pragma unroll
                for (int half = 0; half < 2; half++) {
                    int row = bm + wm * 64 + mi * 16 + r + half * 8;
                    int b = row >> 10, t = row & 1023;
                    float vals[NT][2];
#pragma unroll
                    for (int ni = 0; ni < NT; ni++) {
                        int colt = bn + wn * WNT + ni * 8 + c * 2;
                        vals[ni][0] = acc[mi][ni][half * 2 + 0] + bias[colt];
                        vals[ni][1] = acc[mi][ni][half * 2 + 1] + bias[colt + 1];
                    }
                    if (doRot) {
#pragma unroll
                        for (int ni = 0; ni < 2; ni++) {
                            int j0 = ni * 8 + c * 2;
                            float c0 = g_ropec[t * 16 + j0], s0 = g_ropes[t * 16 + j0];
                            float c1 = g_ropec[t * 16 + j0 + 1], s1 = g_ropes[t * 16 + j0 + 1];
                            float x0 = vals[ni][0], x1 = vals[ni][1];
                            float y0 = vals[ni + 2][0], y1 = vals[ni + 2][1];
                            vals[ni][0] = x0 * c0 - y0 * s0;
                            vals[ni][1] = x1 * c1 - y1 * s1;
                            vals[ni + 2][0] = y0 * c0 + x0 * s0;
                            vals[ni + 2][1] = y1 * c1 + x1 * s1;
                        }
                    }
#pragma unroll
                    for (int ni = 0; ni < NT; ni++) {
                        int colt = bn + wn * WNT + ni * 8 + c * 2;
                        int h = colt >> 6, d = colt & 63;
                        unsigned* Ow = (unsigned*)Out;
                        size_t hidx = (((size_t)b * Hz + h) * Tz + t) * HSz + d;
                        Ow[hidx >> 1] = packh2(vals[ni][0], vals[ni][1]);
                    }
                }
            }
        } else {
#pragma unroll
            for (int mi = 0; mi < 4; mi++) {
#pragma unroll
                for (int ni = 0; ni < NT; ni++) {
#pragma unroll
                    for (int half = 0; half < 2; half++) {
                        int row = bm + wm * 64 + mi * 16 + r + half * 8;
                        int colt = bn + wn * WNT + ni * 8 + c * 2;
                        float v0 = acc[mi][ni][half * 2 + 0];
                        float v1 = acc[mi][ni][half * 2 + 1];
                        if constexpr (MODE == 1) {
                            int t = row & 1023;
                            float gm = gamma[t];
                            float2 o = make_float2((v0 + bias[colt]) * gm,
                                                   (v1 + bias[colt + 1]) * gm);
                            *(float2*)(Out + (size_t)row * Cz + colt) = o;
                        } else if constexpr (MODE == 2) {
                            unsigned* Sw = (unsigned*)Out;
                            size_t hidx = (size_t)z * Tz * Tz + (size_t)row * Tz + colt;
                            Sw[hidx >> 1] = packh2(v0 * 0.125f, v1 * 0.125f);
                        } else {
                            int b = z >> 4, g = z & 15;
                            unsigned* yw = (unsigned*)Out;
                            size_t hidx = ((size_t)b * Tz + row) * Cz + g * HSz + colt;
                            yw[hidx >> 1] = packh2(v0, v1);
                        }
                    }
                }
            }
        }
        __syncthreads();
    }
}

// ---------------- softmax + w + tensor-core head-mix (causal store skip) -------
__global__ __launch_bounds__(512) void softmax_mix(
    const __half* __restrict__ S, unsigned* __restrict__ M2w,
    const float* __restrict__ tw, const float* __restrict__ alpha,
    const float* __restrict__ beta, const float* __restrict__ Wmix)
{
    constexpr int PADH = 1032;
    __shared__ __half P[16][PADH];
    __shared__ __half Wh[16][24];
    int t = blockIdx.x, b = blockIdx.y;
    int tid = threadIdx.x, lane = tid & 31, h = tid >> 5;

    if (tid < 256) Wh[tid >> 4][tid & 15] = __float2half(Wmix[tid]);

    const uint4* row = (const uint4*)(S + (((size_t)b * Hz + h) * Tz + t) * Tz);
    float vals[32];
    float mx = -1e30f;
#pragma unroll
    for (int j = 0; j < 4; j++) {
        uint4 u = row[lane + j * 32];
        unsigned uu[4] = {u.x, u.y, u.z, u.w};
#pragma unroll
        for (int q = 0; q < 4; q++) {
            float2 f = __half22float2(*(__half2*)&uu[q]);
            vals[j * 8 + 2 * q]     = f.x;
            vals[j * 8 + 2 * q + 1] = f.y;
            mx = fmaxf(mx, fmaxf(f.x, f.y));
        }
    }
#pragma unroll
    for (int o = 16; o; o >>= 1) mx = fmaxf(mx, __shfl_xor_sync(~0u, mx, o));
    float sum = 0.f;
#pragma unroll
    for (int l = 0; l < 32; l++) {
        vals[l] = __expf(vals[l] - mx);
        sum += vals[l];
    }
#pragma unroll
    for (int o = 16; o; o >>= 1) sum += __shfl_xor_sync(~0u, sum, o);
    float bt = beta[h * Tz + t] / sum;
#pragma unroll
    for (int j = 0; j < 4; j++) {
        int s0 = (lane + j * 32) * 8;
        unsigned wv[4];
#pragma unroll
        for (int q = 0; q < 4; q++) {
            int sa = s0 + 2 * q, sb = s0 + 2 * q + 1;
            float wa = 0.f, wb = 0.f;
            if (sa <= t) wa = tw[h * Tz + 1023 + sa - t] * alpha[h * Tz + sa] * bt;
            if (sb <= t) wb = tw[h * Tz + 1023 + sb - t] * alpha[h * Tz + sb] * bt;
            wv[q] = packh2(vals[j * 8 + 2 * q] * wa, vals[j * 8 + 2 * q + 1] * wb);
        }
        *(uint4*)&P[h][s0] = *(uint4*)wv;
    }
    __syncthreads();
    {
        // PV only reads s < (t & ~127) + 128; blocks beyond are never read -> skip.
        int slimit = (t & ~127) + 128;
        if (h * 64 < slimit) {
            int r = lane >> 2, c = lane & 3;
            unsigned arow = (lane & 7) + ((lane >> 3) & 1) * 8;
            unsigned acol = (lane >> 4) * 8;
            unsigned aaddr = (unsigned)__cvta_generic_to_shared(&Wh[arow][acol]);
            unsigned af0, af1, af2, af3;
            asm volatile("ldmatrix.sync.aligned.m8n8.x4.shared.b16 {%0,%1,%2,%3},[%4];"
                         : "=r"(af0), "=r"(af1), "=r"(af2), "=r"(af3) : "r"(aaddr));
            size_t orow0 = ((size_t)b * Hz) * Tz + t;
#pragma unroll
            for (int n8 = 0; n8 < 8; n8++) {
                int s0 = h * 64 + n8 * 8;
                unsigned baddr = (unsigned)__cvta_generic_to_shared(&P[lane & 15][s0]);
                unsigned bf0, bf1;
                asm volatile("ldmatrix.sync.aligned.m8n8.x2.trans.shared.b16 {%0,%1},[%2];"
                             : "=r"(bf0), "=r"(bf1) : "r"(baddr));
                float d0 = 0.f, d1 = 0.f, d2 = 0.f, d3 = 0.f;
                asm volatile(
                    "mma.sync.aligned.m16n8k16.row.col.f32.f16.f16.f32 "
                    "{%0,%1,%2,%3},{%4,%5,%6,%7},{%8,%9},{%0,%1,%2,%3};"
                    : "+f"(d0), "+f"(d1), "+f"(d2), "+f"(d3)
                    : "r"(af0), "r"(af1), "r"(af2), "r"(af3), "r"(bf0), "r"(bf1));
                int sw = (s0 >> 1) + c;
                M2w[(orow0 + (size_t)r * Tz) * (Tz / 2) + sw]       = packh2(d0, d1);
                M2w[(orow0 + (size_t)(r + 8) * Tz) * (Tz / 2) + sw] = packh2(d2, d3);
            }
        }
    }
}

// ---------------- launch ----------------
extern "C" void kernel_launch(void* const* d_in, const int* in_sizes, int n_in,
                              void* d_out, int out_size) {
    const float* x          = (const float*)d_in[0];
    const float* time_w     = (const float*)d_in[1];
    const float* time_alpha = (const float*)d_in[2];
    const float* time_beta  = (const float*)d_in[3];
    const float* time_gamma = (const float*)d_in[4];
    const float* Wq = (const float*)d_in[5];
    const float* bq = (const float*)d_in[6];
    const float* Wk = (const float*)d_in[7];
    const float* bk = (const float*)d_in[8];
    const float* Wv = (const float*)d_in[9];
    const float* bv = (const float*)d_in[10];
    const float* Wmix = (const float*)d_in[11];
    const float* Wo = (const float*)d_in[12];
    const float* bo = (const float*)d_in[13];
    float* out = (float*)d_out;

    __half *xsh, *Wqh, *Wkh, *Wvh, *Woh, *qh, *kh, *vh, *S, *M2, *yh;
    cudaGetSymbolAddress((void**)&xsh, g_xsh);
    cudaGetSymbolAddress((void**)&Wqh, g_Wqh);
    cudaGetSymbolAddress((void**)&Wkh, g_Wkh);
    cudaGetSymbolAddress((void**)&Wvh, g_Wvh);
    cudaGetSymbolAddress((void**)&Woh, g_Woh);
    cudaGetSymbolAddress((void**)&qh, g_qh);
    cudaGetSymbolAddress((void**)&kh, g_kh);
    cudaGetSymbolAddress((void**)&vh, g_vh);
    cudaGetSymbolAddress((void**)&S,  g_S);
    cudaGetSymbolAddress((void**)&M2, g_M2);
    cudaGetSymbolAddress((void**)&yh, g_yh);

    constexpr int SM128 = 4 * 128 * 80 + 4 * 32 * 136 * 2;   // 75776
    constexpr int SMSC  = 4 * 128 * 80 + 4 * 128 * 80;       // 81920
    constexpr int SM64  = 4 * 128 * 80 + 4 * 32 * 72 * 2;    // 59392

    cudaFuncSetAttribute((const void*)gemm_h<0, 128, 1024, 1024, 1024, 0, 24, 16, 1, 0>,
                         cudaFuncAttributeMaxDynamicSharedMemorySize, SM128);
    cudaFuncSetAttribute((const void*)gemm_h<1, 128, 1024, 1024, 1024, 0, 8, 16, 1, 0>,
                         cudaFuncAttributeMaxDynamicSharedMemorySize, SM128);
    cudaFuncSetAttribute((const void*)gemm_h<2, 128, 64, 64, 64, 1, 8, 8, 32, 0>,
                         cudaFuncAttributeMaxDynamicSharedMemorySize, SMSC);
    cudaFuncSetAttribute((const void*)gemm_h<3, 64, 1024, 1024, 64, 0, 1, 8, 32, 1>,
                         cudaFuncAttributeMaxDynamicSharedMemorySize, SM64);

    rope_tab<<<64, 256>>>();
    shift_cvt4<<<(Bz * Tz * Cz / 4) / 256, 256>>>(x, xsh);
    wcvt<<<(4 * 131072) / 256, 256>>>(Wq, Wk, Wv, Wo, Wqh, Wkh, Wvh, Woh);

    // QKV: exact grid (384 CTAs)
    gemm_h<0, 128, 1024, 1024, 1024, 0, 24, 16, 1, 0><<<384, 256, SM128>>>(
        xsh, Wqh, Wkh, Wvh, bq, bk, bv, (float*)qh, (float*)kh, (float*)vh, nullptr);

    // scores: 2048 tiles on 304 persistent CTAs
    gemm_h<2, 128, 64, 64, 64, 1, 8, 8, 32, 0><<<304, 256, SMSC>>>(
        qh, kh, nullptr, nullptr, nullptr, nullptr, nullptr, (float*)S, nullptr, nullptr, nullptr);

    softmax_mix<<<dim3(Tz, Bz), 512>>>(S, (unsigned*)M2, time_w, time_alpha,
                                       time_beta, Wmix);

    // PV: exact grid, CAUSAL (k limited to diagonal tile)
    gemm_h<3, 64, 1024, 1024, 64, 0, 1, 8, 32, 1><<<256, 256, SM64>>>(
        M2, vh, nullptr, nullptr, nullptr, nullptr, nullptr, (float*)yh, nullptr, nullptr, nullptr);

    // output: exact grid
    gemm_h<1, 128, 1024, 1024, 1024, 0, 8, 16, 1, 0><<<128, 256, SM128>>>(
        yh, Woh, nullptr, nullptr, bo, nullptr, nullptr, out, nullptr, nullptr, time_gamma);
}